// round 1
// baseline (speedup 1.0000x reference)
#include <cuda_runtime.h>
#include <cstdint>

#define HAT_EPS 1e-5f
#define ALPHA_CAP 2000000

// global accumulators: [0]=sum softplus(pos), [1]=sum softplus(-neg), [2]=sum 1/(rank+1)
static __device__ double g_acc[3];
static __device__ float  g_inv_alpha[ALPHA_CAP];

__global__ void hat_init_kernel() {
    g_acc[0] = 0.0; g_acc[1] = 0.0; g_acc[2] = 0.0;
}

// ---------------------------------------------------------------------------
// Prepass: inv_alpha[i] = 1 / max(1 - ||h_i||^2, eps), D = 64, 16 lanes/node
// ---------------------------------------------------------------------------
__global__ void __launch_bounds__(256) hat_alpha_kernel(const float* __restrict__ h, int N) {
    int tid  = blockIdx.x * blockDim.x + threadIdx.x;
    int node = tid >> 4;
    int sub  = tid & 15;
    if (node >= N) return;
    const float4* hp = (const float4*)(h + (size_t)node * 64);
    float4 a = hp[sub];
    float s = a.x * a.x + a.y * a.y + a.z * a.z + a.w * a.w;
    s += __shfl_xor_sync(0xffffffffu, s, 8);
    s += __shfl_xor_sync(0xffffffffu, s, 4);
    s += __shfl_xor_sync(0xffffffffu, s, 2);
    s += __shfl_xor_sync(0xffffffffu, s, 1);
    if (sub == 0) g_inv_alpha[node] = 1.0f / fmaxf(1.0f - s, HAT_EPS);
}

__device__ __forceinline__ float hat_softplus(float x) {
    // log(1 + exp(x)); for large x this is x (exp fine up to ~88, scores <~60)
    if (x > 30.0f) return x;
    return log1pf(__expf(x));
}

__device__ __forceinline__ void hat_block_reduce_atomic(float sp_pos, float sp_neg,
                                                        float inv_rank) {
    __shared__ float s_a[16], s_b[16], s_c[16];
    int lane = threadIdx.x & 31;
    int wid  = threadIdx.x >> 5;
    if (lane == 0) { s_a[wid] = sp_pos; s_b[wid] = sp_neg; s_c[wid] = inv_rank; }
    __syncthreads();
    if (wid == 0) {
        int nw = blockDim.x >> 5;
        float a = (lane < nw) ? s_a[lane] : 0.0f;
        float b = (lane < nw) ? s_b[lane] : 0.0f;
        float c = (lane < nw) ? s_c[lane] : 0.0f;
        #pragma unroll
        for (int off = 8; off >= 1; off >>= 1) {
            a += __shfl_xor_sync(0xffffffffu, a, off);
            b += __shfl_xor_sync(0xffffffffu, b, off);
            c += __shfl_xor_sync(0xffffffffu, c, off);
        }
        if (lane == 0) {
            atomicAdd(&g_acc[0], (double)a);
            atomicAdd(&g_acc[1], (double)b);
            atomicAdd(&g_acc[2], (double)c);
        }
    }
}

// ---------------------------------------------------------------------------
// Main kernel (NN odd): one warp per positive group (pos edge + NN negatives).
// Half-warps (16 lanes, float4/lane) process distances t = half, half+2, ...
// Half 0: t=0(pos),2,4  Half 1: t=1,3,5  (for NN=5)
// ---------------------------------------------------------------------------
template <int NN>
__global__ void __launch_bounds__(512) hat_main_kernel(
    const float* __restrict__ h,
    const int* __restrict__ ps, const int* __restrict__ pd,
    const int* __restrict__ ns, const int* __restrict__ nd,
    int E_pos)
{
    static_assert(NN % 2 == 1, "NN must be odd");
    constexpr int ND = (NN + 1) / 2;  // distances per half (both halves equal: NN+1 even)

    const int lane = threadIdx.x & 31;
    const int wid  = threadIdx.x >> 5;
    const int g    = blockIdx.x * (blockDim.x >> 5) + wid;
    const int half = lane >> 4;
    const int sub  = lane & 15;

    float sp_pos = 0.0f, sp_neg = 0.0f, inv_rank = 0.0f;

    if (g < E_pos) {
        float sc[ND];
        #pragma unroll
        for (int k = 0; k < ND; k++) {
            const int t = half + 2 * k;            // 0..NN
            int src, dst;
            if (t == 0) { src = __ldg(&ps[g]); dst = __ldg(&pd[g]); }
            else {
                int e = g * NN + (t - 1);
                src = __ldg(&ns[e]); dst = __ldg(&nd[e]);
            }
            const float4* up = (const float4*)(h + (size_t)src * 64);
            const float4* vp = (const float4*)(h + (size_t)dst * 64);
            float4 a = __ldg(&up[sub]);
            float4 b = __ldg(&vp[sub]);
            float dx = a.x - b.x, dy = a.y - b.y, dz = a.z - b.z, dw = a.w - b.w;
            float s = fmaf(dx, dx, fmaf(dy, dy, fmaf(dz, dz, dw * dw)));
            s += __shfl_xor_sync(0xffffffffu, s, 8);
            s += __shfl_xor_sync(0xffffffffu, s, 4);
            s += __shfl_xor_sync(0xffffffffu, s, 2);
            s += __shfl_xor_sync(0xffffffffu, s, 1);
            float score = 0.0f;
            if (sub == 0) {
                float ia = g_inv_alpha[src];
                float ib = g_inv_alpha[dst];
                float gam = fmaxf(fmaf(2.0f * s, ia * ib, 1.0f), 1.0f + HAT_EPS);
                float t2  = fmaf(gam, gam, -1.0f);
                float d   = __logf(gam + __fsqrt_rn(t2));
                score = d * d;
            }
            sc[k] = score;
        }

        // broadcast pos score (lane 0 holds sc[0] = distance t=0)
        float pos = __shfl_sync(0xffffffffu, sc[0], 0);

        if (sub == 0) {
            int   cnt = 0;
            float spn = 0.0f;
            #pragma unroll
            for (int k = 0; k < ND; k++) {
                const int t = half + 2 * k;
                if (t >= 1) {
                    cnt += (sc[k] < pos) ? 1 : 0;   // neg_logit > pos_logit <=> ns < ps
                    spn += hat_softplus(-sc[k]);
                }
            }
            // fold lane 16's contribution into lane 0
            cnt += __shfl_down_sync(0x00010001u, cnt, 16);
            spn += __shfl_down_sync(0x00010001u, spn, 16);
            if (half == 0) {
                sp_neg   = spn;
                sp_pos   = hat_softplus(pos);
                inv_rank = 1.0f / (float)(cnt + 1);
            }
        }
    }

    hat_block_reduce_atomic(sp_pos, sp_neg, inv_rank);
}

// ---------------------------------------------------------------------------
// Generic fallback (any nn): one warp per group, sequential distances,
// no precomputed alpha (self-contained).
// ---------------------------------------------------------------------------
__global__ void __launch_bounds__(256) hat_generic_kernel(
    const float* __restrict__ h,
    const int* __restrict__ ps, const int* __restrict__ pd,
    const int* __restrict__ ns, const int* __restrict__ nd,
    int E_pos, int nn)
{
    const int lane = threadIdx.x & 31;
    const int wid  = threadIdx.x >> 5;
    const int g    = blockIdx.x * (blockDim.x >> 5) + wid;

    float sp_pos = 0.0f, sp_neg = 0.0f, inv_rank = 0.0f;

    if (g < E_pos) {
        float pos = 0.0f;
        int   cnt = 0;
        for (int t = 0; t <= nn; t++) {
            int src, dst;
            if (t == 0) { src = ps[g]; dst = pd[g]; }
            else {
                size_t e = (size_t)g * nn + (t - 1);
                src = ns[e]; dst = nd[e];
            }
            const float2* up = (const float2*)(h + (size_t)src * 64);
            const float2* vp = (const float2*)(h + (size_t)dst * 64);
            float2 a = up[lane], b = vp[lane];
            float dx = a.x - b.x, dy = a.y - b.y;
            float sq = dx * dx + dy * dy;
            float uu = a.x * a.x + a.y * a.y;
            float vv = b.x * b.x + b.y * b.y;
            #pragma unroll
            for (int off = 16; off >= 1; off >>= 1) {
                sq += __shfl_xor_sync(0xffffffffu, sq, off);
                uu += __shfl_xor_sync(0xffffffffu, uu, off);
                vv += __shfl_xor_sync(0xffffffffu, vv, off);
            }
            if (lane == 0) {
                float alpha = fmaxf(1.0f - uu, HAT_EPS);
                float beta  = fmaxf(1.0f - vv, HAT_EPS);
                float gam   = fmaxf(1.0f + 2.0f * sq / (alpha * beta), 1.0f + HAT_EPS);
                float d     = __logf(gam + __fsqrt_rn(fmaf(gam, gam, -1.0f)));
                float sc    = d * d;
                if (t == 0) { pos = sc; sp_pos = hat_softplus(sc); }
                else {
                    sp_neg += hat_softplus(-sc);
                    cnt += (sc < pos) ? 1 : 0;
                }
            }
        }
        if (lane == 0) inv_rank = 1.0f / (float)(cnt + 1);
    }

    hat_block_reduce_atomic(sp_pos, sp_neg, inv_rank);
}

__global__ void hat_fin_kernel(float* out, int E_pos, int E_neg, int out_size) {
    double loss = g_acc[0] / (double)E_pos + g_acc[1] / (double)E_neg;
    out[0] = (float)loss;
    if (out_size > 1) out[1] = (float)(g_acc[2] / (double)E_pos);
}

extern "C" void kernel_launch(void* const* d_in, const int* in_sizes, int n_in,
                              void* d_out, int out_size) {
    const float* h  = (const float*)d_in[0];
    const int*   ps = (const int*)d_in[1];
    const int*   pd = (const int*)d_in[2];
    const int*   ns = (const int*)d_in[3];
    const int*   nd = (const int*)d_in[4];

    const int E_pos = in_sizes[1];
    const int E_neg = in_sizes[3];
    const int nn    = (E_pos > 0) ? (E_neg / E_pos) : 1;
    const int N     = in_sizes[0] / 64;   // D = 64 (fixed by dataset)

    hat_init_kernel<<<1, 1>>>();

    if (nn == 5 && N <= ALPHA_CAP) {
        int a_threads = N * 16;
        hat_alpha_kernel<<<(a_threads + 255) / 256, 256>>>(h, N);
        const int gpb = 512 / 32;  // 16 groups per block
        hat_main_kernel<5><<<(E_pos + gpb - 1) / gpb, 512>>>(h, ps, pd, ns, nd, E_pos);
    } else {
        const int gpb = 256 / 32;
        hat_generic_kernel<<<(E_pos + gpb - 1) / gpb, 256>>>(h, ps, pd, ns, nd, E_pos, nn);
    }

    hat_fin_kernel<<<1, 1>>>((float*)d_out, E_pos, E_neg, out_size);
}

// round 2
// speedup vs baseline: 1.0054x; 1.0054x over previous
#include <cuda_runtime.h>
#include <cstdint>

#define HAT_EPS 1e-5f

// accumulators: [0]=sum softplus(pos), [1]=sum softplus(-neg), [2]=sum 1/(rank+1)
static __device__ double g_acc[3];          // zero-initialized at module load
static __device__ unsigned int g_done;      // ticket counter, reset by last block

__device__ __forceinline__ float hat_softplus(float x) {
    if (x > 30.0f) return x;
    return log1pf(__expf(x));
}

// ---------------------------------------------------------------------------
// Fully fused kernel (NN odd): one warp per positive group (pos + NN negs).
// Half-warps (16 lanes, float4/lane) process distances t = half, half+2, ...
// alpha/beta computed inline from the gathered rows (no prepass, no extra
// gathers). init (static zero / last-block reset) and finalize fused in.
// ---------------------------------------------------------------------------
template <int NN>
__global__ void __launch_bounds__(256) hat_fused_kernel(
    const float* __restrict__ h,
    const int* __restrict__ ps, const int* __restrict__ pd,
    const int* __restrict__ ns, const int* __restrict__ nd,
    int E_pos, int E_neg, float* __restrict__ out, int out_size)
{
    static_assert(NN % 2 == 1, "NN must be odd");
    constexpr int ND = (NN + 1) / 2;   // distances per half-warp

    const int lane = threadIdx.x & 31;
    const int wid  = threadIdx.x >> 5;
    const int g    = blockIdx.x * (blockDim.x >> 5) + wid;
    const int half = lane >> 4;
    const int sub  = lane & 15;

    float sp_pos = 0.0f, sp_neg = 0.0f, inv_rank = 0.0f;

    if (g < E_pos) {
        // ---- preload all 2 + 2*NN edge indices into lanes, one latency ----
        int idx = 0;
        if (lane == 0)                 idx = __ldg(&ps[g]);
        else if (lane == 1)            idx = __ldg(&pd[g]);
        else if (lane < 2 + NN)        idx = __ldg(&ns[g * NN + (lane - 2)]);
        else if (lane < 2 + 2 * NN)    idx = __ldg(&nd[g * NN + (lane - 2 - NN)]);

        float sc[ND];
        #pragma unroll
        for (int k = 0; k < ND; k++) {
            const int t  = half + 2 * k;                  // 0..NN
            const int sl = (t == 0) ? 0 : (t + 1);        // src index lane
            const int dl = (t == 0) ? 1 : (t + 1 + NN);   // dst index lane
            int src = __shfl_sync(0xffffffffu, idx, sl);
            int dst = __shfl_sync(0xffffffffu, idx, dl);

            const float4* up = (const float4*)(h + (size_t)src * 64);
            const float4* vp = (const float4*)(h + (size_t)dst * 64);
            float4 a = __ldg(&up[sub]);
            float4 b = __ldg(&vp[sub]);

            float dx = a.x - b.x, dy = a.y - b.y, dz = a.z - b.z, dw = a.w - b.w;
            float sq = fmaf(dx, dx, fmaf(dy, dy, fmaf(dz, dz, dw * dw)));
            float uu = fmaf(a.x, a.x, fmaf(a.y, a.y, fmaf(a.z, a.z, a.w * a.w)));
            float vv = fmaf(b.x, b.x, fmaf(b.y, b.y, fmaf(b.z, b.z, b.w * b.w)));
            #pragma unroll
            for (int off = 8; off >= 1; off >>= 1) {
                sq += __shfl_xor_sync(0xffffffffu, sq, off);
                uu += __shfl_xor_sync(0xffffffffu, uu, off);
                vv += __shfl_xor_sync(0xffffffffu, vv, off);
            }
            float score = 0.0f;
            if (sub == 0) {
                float ab  = fmaxf(1.0f - uu, HAT_EPS) * fmaxf(1.0f - vv, HAT_EPS);
                float gam = fmaxf(1.0f + __fdividef(2.0f * sq, ab), 1.0f + HAT_EPS);
                float d   = __logf(gam + __fsqrt_rn(fmaf(gam, gam, -1.0f)));
                score = d * d;
            }
            sc[k] = score;
        }

        // positive score lives in lane 0's sc[0]
        float pos = __shfl_sync(0xffffffffu, sc[0], 0);

        if (sub == 0) {
            int   cnt = 0;
            float spn = 0.0f;
            #pragma unroll
            for (int k = 0; k < ND; k++) {
                const int t = half + 2 * k;
                if (t >= 1) {
                    cnt += (sc[k] < pos) ? 1 : 0;   // -ns > -ps  <=>  ns < ps
                    spn += hat_softplus(-sc[k]);
                }
            }
            // fold lane 16 into lane 0
            cnt += __shfl_down_sync(0x00010001u, cnt, 16);
            spn += __shfl_down_sync(0x00010001u, spn, 16);
            if (half == 0) {
                sp_neg   = spn;
                sp_pos   = hat_softplus(pos);
                inv_rank = 1.0f / (float)(cnt + 1);
            }
        }
    }

    // ---- block reduction -> global double atomics ----
    __shared__ float s_a[8], s_b[8], s_c[8];
    __shared__ bool  s_last;
    if (lane == 0) { s_a[wid] = sp_pos; s_b[wid] = sp_neg; s_c[wid] = inv_rank; }
    __syncthreads();
    if (wid == 0) {
        const int nw = blockDim.x >> 5;
        float a = (lane < nw) ? s_a[lane] : 0.0f;
        float b = (lane < nw) ? s_b[lane] : 0.0f;
        float c = (lane < nw) ? s_c[lane] : 0.0f;
        #pragma unroll
        for (int off = 4; off >= 1; off >>= 1) {
            a += __shfl_xor_sync(0xffffffffu, a, off);
            b += __shfl_xor_sync(0xffffffffu, b, off);
            c += __shfl_xor_sync(0xffffffffu, c, off);
        }
        if (lane == 0) {
            atomicAdd(&g_acc[0], (double)a);
            atomicAdd(&g_acc[1], (double)b);
            atomicAdd(&g_acc[2], (double)c);
            __threadfence();
            unsigned ticket = atomicAdd(&g_done, 1u);
            s_last = (ticket == gridDim.x - 1);
        }
    }
    __syncthreads();

    // ---- last block finalizes and resets state for the next graph replay ----
    if (s_last && threadIdx.x == 0) {
        volatile double* acc = (volatile double*)g_acc;
        double a = acc[0], b = acc[1], c = acc[2];
        out[0] = (float)(a / (double)E_pos + b / (double)E_neg);
        if (out_size > 1) out[1] = (float)(c / (double)E_pos);
        g_acc[0] = 0.0; g_acc[1] = 0.0; g_acc[2] = 0.0;
        g_done = 0u;
        __threadfence();
    }
}

// ---------------------------------------------------------------------------
// Generic fallback (any nn), self-contained: init, compute, fin.
// ---------------------------------------------------------------------------
__global__ void hat_init_kernel() {
    g_acc[0] = 0.0; g_acc[1] = 0.0; g_acc[2] = 0.0;
}

__global__ void __launch_bounds__(256) hat_generic_kernel(
    const float* __restrict__ h,
    const int* __restrict__ ps, const int* __restrict__ pd,
    const int* __restrict__ ns, const int* __restrict__ nd,
    int E_pos, int nn)
{
    const int lane = threadIdx.x & 31;
    const int wid  = threadIdx.x >> 5;
    const int g    = blockIdx.x * (blockDim.x >> 5) + wid;

    float sp_pos = 0.0f, sp_neg = 0.0f, inv_rank = 0.0f;

    if (g < E_pos) {
        float pos = 0.0f;
        int   cnt = 0;
        for (int t = 0; t <= nn; t++) {
            int src, dst;
            if (t == 0) { src = ps[g]; dst = pd[g]; }
            else {
                size_t e = (size_t)g * nn + (t - 1);
                src = ns[e]; dst = nd[e];
            }
            const float2* up = (const float2*)(h + (size_t)src * 64);
            const float2* vp = (const float2*)(h + (size_t)dst * 64);
            float2 a = up[lane], b = vp[lane];
            float dx = a.x - b.x, dy = a.y - b.y;
            float sq = dx * dx + dy * dy;
            float uu = a.x * a.x + a.y * a.y;
            float vv = b.x * b.x + b.y * b.y;
            #pragma unroll
            for (int off = 16; off >= 1; off >>= 1) {
                sq += __shfl_xor_sync(0xffffffffu, sq, off);
                uu += __shfl_xor_sync(0xffffffffu, uu, off);
                vv += __shfl_xor_sync(0xffffffffu, vv, off);
            }
            if (lane == 0) {
                float alpha = fmaxf(1.0f - uu, HAT_EPS);
                float beta  = fmaxf(1.0f - vv, HAT_EPS);
                float gam   = fmaxf(1.0f + 2.0f * sq / (alpha * beta), 1.0f + HAT_EPS);
                float d     = __logf(gam + __fsqrt_rn(fmaf(gam, gam, -1.0f)));
                float scv   = d * d;
                if (t == 0) { pos = scv; sp_pos = hat_softplus(scv); }
                else {
                    sp_neg += hat_softplus(-scv);
                    cnt += (scv < pos) ? 1 : 0;
                }
            }
        }
        if (lane == 0) inv_rank = 1.0f / (float)(cnt + 1);
    }

    __shared__ float s_a[8], s_b[8], s_c[8];
    if (lane == 0) { s_a[wid] = sp_pos; s_b[wid] = sp_neg; s_c[wid] = inv_rank; }
    __syncthreads();
    if (wid == 0) {
        const int nw = blockDim.x >> 5;
        float a = (lane < nw) ? s_a[lane] : 0.0f;
        float b = (lane < nw) ? s_b[lane] : 0.0f;
        float c = (lane < nw) ? s_c[lane] : 0.0f;
        #pragma unroll
        for (int off = 4; off >= 1; off >>= 1) {
            a += __shfl_xor_sync(0xffffffffu, a, off);
            b += __shfl_xor_sync(0xffffffffu, b, off);
            c += __shfl_xor_sync(0xffffffffu, c, off);
        }
        if (lane == 0) {
            atomicAdd(&g_acc[0], (double)a);
            atomicAdd(&g_acc[1], (double)b);
            atomicAdd(&g_acc[2], (double)c);
        }
    }
}

__global__ void hat_fin_kernel(float* out, int E_pos, int E_neg, int out_size) {
    double loss = g_acc[0] / (double)E_pos + g_acc[1] / (double)E_neg;
    out[0] = (float)loss;
    if (out_size > 1) out[1] = (float)(g_acc[2] / (double)E_pos);
}

extern "C" void kernel_launch(void* const* d_in, const int* in_sizes, int n_in,
                              void* d_out, int out_size) {
    const float* h  = (const float*)d_in[0];
    const int*   ps = (const int*)d_in[1];
    const int*   pd = (const int*)d_in[2];
    const int*   ns = (const int*)d_in[3];
    const int*   nd = (const int*)d_in[4];

    const int E_pos = in_sizes[1];
    const int E_neg = in_sizes[3];
    const int nn    = (E_pos > 0) ? (E_neg / E_pos) : 1;

    if (nn == 5) {
        const int gpb = 256 / 32;  // 8 groups (warps) per block
        const int blocks = (E_pos + gpb - 1) / gpb;
        hat_fused_kernel<5><<<blocks, 256>>>(h, ps, pd, ns, nd,
                                             E_pos, E_neg, (float*)d_out, out_size);
    } else {
        hat_init_kernel<<<1, 1>>>();
        const int gpb = 256 / 32;
        hat_generic_kernel<<<(E_pos + gpb - 1) / gpb, 256>>>(h, ps, pd, ns, nd, E_pos, nn);
        hat_fin_kernel<<<1, 1>>>((float*)d_out, E_pos, E_neg, out_size);
    }
}